// round 15
// baseline (speedup 1.0000x reference)
#include <cuda_runtime.h>
#include <cuda_bf16.h>
#include <cuda_fp16.h>
#include <cstdint>
#include <math.h>

#define MM 16384   // B*S = 32*512

// ---------------- scratch (device globals; no allocation allowed) -------------
__device__ float g_y[MM * 512];
__device__ float g_x2[MM * 512];

__device__ __half g_qkvh[MM * 1536];
__device__ __half g_xh[MM * 512];
__device__ __half g_ah[MM * 512];      // attention out
__device__ __half g_x2h[MM * 512];
__device__ __half g_hh[MM * 2048];     // ffn hidden
__device__ __half g_w1h[1536 * 512];
__device__ __half g_w2h[512 * 512];
__device__ __half g_w3h[2048 * 512];
__device__ __half g_w4h[512 * 2048];

// ---------------- helpers ----------------------------------------------------
__device__ __forceinline__ uint32_t smem_u32(const void* p) {
    uint32_t a;
    asm("{ .reg .u64 t; cvta.to.shared.u64 t, %1; cvt.u32.u64 %0, t; }"
        : "=r"(a) : "l"(p));
    return a;
}
#define SWZ128(o) ((o) ^ (((o) >> 3) & 0x70))

__device__ __forceinline__ void cp16(uint32_t dst, const void* src) {
    asm volatile("cp.async.cg.shared.global [%0], [%1], 16;"
                 :: "r"(dst), "l"(src) : "memory");
}
#define LDSM4(r, addr) \
    asm volatile("ldmatrix.sync.aligned.m8n8.x4.shared.b16 {%0,%1,%2,%3}, [%4];" \
                 : "=r"((r)[0]), "=r"((r)[1]), "=r"((r)[2]), "=r"((r)[3]) : "r"(addr))
#define LDSM4T(r, addr) \
    asm volatile("ldmatrix.sync.aligned.m8n8.x4.trans.shared.b16 {%0,%1,%2,%3}, [%4];" \
                 : "=r"((r)[0]), "=r"((r)[1]), "=r"((r)[2]), "=r"((r)[3]) : "r"(addr))

__device__ __forceinline__ void mma_f16(float* c, const uint32_t* a,
                                        uint32_t b0, uint32_t b1) {
    asm volatile(
        "mma.sync.aligned.m16n8k16.row.col.f32.f16.f16.f32 "
        "{%0,%1,%2,%3}, {%4,%5,%6,%7}, {%8,%9}, {%0,%1,%2,%3};"
        : "+f"(c[0]), "+f"(c[1]), "+f"(c[2]), "+f"(c[3])
        : "r"(a[0]), "r"(a[1]), "r"(a[2]), "r"(a[3]), "r"(b0), "r"(b1));
}
__device__ __forceinline__ uint32_t packh2(float a, float b) {
    __half2 h = __floats2half2_rn(a, b);
    return *reinterpret_cast<uint32_t*>(&h);
}
__device__ __forceinline__ float warp_sum(float v) {
    v += __shfl_xor_sync(0xffffffffu, v, 16);
    v += __shfl_xor_sync(0xffffffffu, v, 8);
    v += __shfl_xor_sync(0xffffffffu, v, 4);
    v += __shfl_xor_sync(0xffffffffu, v, 2);
    v += __shfl_xor_sync(0xffffffffu, v, 1);
    return v;
}

// ---------------- HMMA GEMM (fp16, 128x256 CTA, 512 thr, K-chunk 128) --------
// best measured config (R10): 2-stage, 1 barrier per 128-K chunk.
#define STG_BYTES 98304   // [Ah0 16K][Ah1 16K][Bh0 32K][Bh1 32K]
#define GEMM_SMEM (2 * STG_BYTES)

__device__ __forceinline__ void ld_chunk128(
    uint32_t sbase,
    const __half* __restrict__ A, const __half* __restrict__ B,
    int m0, int n0, int K, int k0, int tid)
{
#pragma unroll
    for (int half = 0; half < 2; half++) {
        const int kh = k0 + half * 64;
        const uint32_t aB = sbase + half * 16384;
        const uint32_t bB = sbase + 32768 + half * 32768;
#pragma unroll
        for (int t = 0; t < 2; t++) {
            int slot = tid + t * 512;
            int r = slot >> 3, c = slot & 7;
            cp16(aB + SWZ128(r * 128 + c * 16), A + (size_t)(m0 + r) * K + kh + c * 8);
        }
#pragma unroll
        for (int t = 0; t < 4; t++) {
            int slot = tid + t * 512;
            int r = slot >> 3, c = slot & 7;
            cp16(bB + SWZ128(r * 128 + c * 16), B + (size_t)(n0 + r) * K + kh + c * 8);
        }
    }
    asm volatile("cp.async.commit_group;" ::: "memory");
}

template <int MODE>
__global__ void __launch_bounds__(512) tc_gemm(
    const __half* __restrict__ A, const __half* __restrict__ B,
    const float* __restrict__ bias, const float* __restrict__ res,
    float* __restrict__ Cf, __half* __restrict__ Ch,
    int M, int N, int K)
{
    extern __shared__ char sm[];
    const uint32_t sb = smem_u32(sm);
    const int tid = threadIdx.x;
    const int wid = tid >> 5, lane = tid & 31;
    const int wm = wid & 1, wn = wid >> 1;   // 2 x 8 warp grid
    const int m0 = blockIdx.y * 128, n0 = blockIdx.x * 256;

    float acc[4][4][4];
#pragma unroll
    for (int i = 0; i < 4; i++)
#pragma unroll
        for (int j = 0; j < 4; j++)
#pragma unroll
            for (int k = 0; k < 4; k++) acc[i][j][k] = 0.f;

    const int nch = K >> 7;
    ld_chunk128(sb, A, B, m0, n0, K, 0, tid);

    const int a_row = wm * 64 + (lane & 15);
    const int a_colb = ((lane >> 4) & 1) * 16;
    const int b_row = wn * 32 + (lane & 7) + ((lane >> 4) & 1) * 8;
    const int b_colb = ((lane >> 3) & 1) * 16;

    for (int c = 0; c < nch; c++) {
        asm volatile("cp.async.wait_group 0;" ::: "memory");
        __syncthreads();
        if (c + 1 < nch)
            ld_chunk128(sb + ((c + 1) & 1) * STG_BYTES,
                        A, B, m0, n0, K, (c + 1) << 7, tid);

        const uint32_t stg = sb + (c & 1) * STG_BYTES;

#pragma unroll
        for (int ks = 0; ks < 8; ks++) {
            const int half = ks >> 2, ksl = ks & 3;
            const uint32_t sA = stg + half * 16384;
            const uint32_t sB = stg + 32768 + half * 32768;
            uint32_t af[4][4];
#pragma unroll
            for (int mt = 0; mt < 4; mt++)
                LDSM4(af[mt], sA + SWZ128((a_row + mt * 16) * 128 + ksl * 32 + a_colb));
            uint32_t bf[2][4];
#pragma unroll
            for (int np = 0; np < 2; np++)
                LDSM4(bf[np], sB + SWZ128((b_row + np * 16) * 128 + ksl * 32 + b_colb));
#pragma unroll
            for (int mt = 0; mt < 4; mt++)
#pragma unroll
                for (int nt = 0; nt < 4; nt++) {
                    const int np = nt >> 1, hf = (nt & 1) * 2;
                    mma_f16(acc[mt][nt], af[mt], bf[np][hf], bf[np][hf + 1]);
                }
        }
    }

    // epilogue
    const int er0 = m0 + wm * 64 + (lane >> 2);
    const int ec0 = n0 + wn * 32 + 2 * (lane & 3);
#pragma unroll
    for (int mt = 0; mt < 4; mt++) {
#pragma unroll
        for (int nt = 0; nt < 4; nt++) {
            const int col = ec0 + nt * 8;
            const float b0 = bias[col], b1 = bias[col + 1];
#pragma unroll
            for (int hh = 0; hh < 2; hh++) {
                const int row = er0 + mt * 16 + hh * 8;
                float v0 = acc[mt][nt][2 * hh + 0] + b0;
                float v1 = acc[mt][nt][2 * hh + 1] + b1;
                size_t off = (size_t)row * N + col;
                if (MODE == 1) {
                    v0 += res[off];
                    v1 += res[off + 1];
                    float2 v; v.x = v0; v.y = v1;
                    *(float2*)(Cf + off) = v;
                } else {
                    if (MODE == 2) {
                        v0 = 0.5f * v0 * (1.0f + erff(v0 * 0.70710678118654752f));
                        v1 = 0.5f * v1 * (1.0f + erff(v1 * 0.70710678118654752f));
                    }
                    *(__half2*)(Ch + off) = __floats2half2_rn(v0, v1);
                }
            }
        }
    }
}

// ---------------- FFN-down GEMM with fused bias+residual+LN2 -----------------
// C-tile 64(M) x 512(N = full row), K-chunk 64, 2-stage. 16 warps as 1 x 16;
// warp w covers cols [w*32, w*32+32). Epilogue computes LN2 per row in-CTA and
// writes the FINAL fp32 output (y2 buffer + LN2 kernel eliminated).
#define LSTG_BYTES 73728   // A 8K | B 64K
#define GEMM_LN_SMEM (2 * LSTG_BYTES)

__global__ void __launch_bounds__(512) tc_gemm_ln(
    const __half* __restrict__ A, const __half* __restrict__ B,
    const float* __restrict__ bias, const float* __restrict__ res,
    const float* __restrict__ g, const float* __restrict__ bl,
    float* __restrict__ out, int K)
{
    extern __shared__ char sm[];
    const uint32_t sb = smem_u32(sm);
    float* part_s = (float*)sm;                 // [64][17] (reuses stage0 region)
    float* part_q = (float*)sm + 64 * 17;       // [64][17]
    float* stat_m = (float*)sm + 2 * 64 * 17;   // [64]
    float* stat_i = stat_m + 64;                // [64]
    const int tid = threadIdx.x;
    const int wid = tid >> 5, lane = tid & 31;
    const int m0 = blockIdx.x * 64;

    float acc[4][4][4];
#pragma unroll
    for (int i = 0; i < 4; i++)
#pragma unroll
        for (int j = 0; j < 4; j++)
#pragma unroll
            for (int k = 0; k < 4; k++) acc[i][j][k] = 0.f;

    const int nch = K >> 6;

    // chunk loader: A 64 rows x 8 cp16, B 512 rows x 8 cp16
    {
        int r = tid >> 3, c = tid & 7;
        cp16(sb + SWZ128(r * 128 + c * 16), A + (size_t)(m0 + r) * K + c * 8);
#pragma unroll
        for (int t = 0; t < 8; t++) {
            int slot = tid + t * 512;
            int rb = slot >> 3, cb = slot & 7;
            cp16(sb + 8192 + SWZ128(rb * 128 + cb * 16), B + (size_t)rb * K + cb * 8);
        }
        asm volatile("cp.async.commit_group;" ::: "memory");
    }

    const int a_row = (lane & 15);
    const int a_colb = ((lane >> 4) & 1) * 16;
    const int b_row = wid * 32 + (lane & 7) + ((lane >> 4) & 1) * 8;
    const int b_colb = ((lane >> 3) & 1) * 16;

    for (int c = 0; c < nch; c++) {
        asm volatile("cp.async.wait_group 0;" ::: "memory");
        __syncthreads();
        if (c + 1 < nch) {
            const int k0 = (c + 1) << 6;
            const uint32_t stn = sb + ((c + 1) & 1) * LSTG_BYTES;
            int r = tid >> 3, cc = tid & 7;
            cp16(stn + SWZ128(r * 128 + cc * 16),
                 A + (size_t)(m0 + r) * K + k0 + cc * 8);
#pragma unroll
            for (int t = 0; t < 8; t++) {
                int slot = tid + t * 512;
                int rb = slot >> 3, cb = slot & 7;
                cp16(stn + 8192 + SWZ128(rb * 128 + cb * 16),
                     B + (size_t)rb * K + k0 + cb * 8);
            }
            asm volatile("cp.async.commit_group;" ::: "memory");
        }

        const uint32_t stg = sb + (c & 1) * LSTG_BYTES;
        const uint32_t sA = stg;
        const uint32_t sB = stg + 8192;

#pragma unroll
        for (int ks = 0; ks < 4; ks++) {
            uint32_t af[4][4];
#pragma unroll
            for (int mt = 0; mt < 4; mt++)
                LDSM4(af[mt], sA + SWZ128((a_row + mt * 16) * 128 + ks * 32 + a_colb));
            uint32_t bf[2][4];
#pragma unroll
            for (int np = 0; np < 2; np++)
                LDSM4(bf[np], sB + SWZ128((b_row + np * 16) * 128 + ks * 32 + b_colb));
#pragma unroll
            for (int mt = 0; mt < 4; mt++)
#pragma unroll
                for (int nt = 0; nt < 4; nt++) {
                    const int np = nt >> 1, hf = (nt & 1) * 2;
                    mma_f16(acc[mt][nt], af[mt], bf[np][hf], bf[np][hf + 1]);
                }
        }
    }

    // ---- epilogue: bias + residual, then LN2, then final store ----
    // value (mt, nt, hh, j): row_local = mt*16 + hh*8 + (lane>>2),
    //                        col = wid*32 + nt*8 + 2*(lane&3) + j
    const int rq = lane >> 2;                 // row group within 8
    const int ec = wid * 32 + 2 * (lane & 3);
#pragma unroll
    for (int mt = 0; mt < 4; mt++) {
#pragma unroll
        for (int hh = 0; hh < 2; hh++) {
            const int row = m0 + mt * 16 + hh * 8 + rq;
            float ps = 0.f, pq = 0.f;
#pragma unroll
            for (int nt = 0; nt < 4; nt++) {
                const int col = ec + nt * 8;
                float v0 = acc[mt][nt][2 * hh + 0] + bias[col] + res[(size_t)row * 512 + col];
                float v1 = acc[mt][nt][2 * hh + 1] + bias[col + 1] + res[(size_t)row * 512 + col + 1];
                acc[mt][nt][2 * hh + 0] = v0;
                acc[mt][nt][2 * hh + 1] = v1;
                ps += v0 + v1;
                pq += v0 * v0 + v1 * v1;
            }
            // reduce over the 4 threads sharing this row (lane&3)
            ps += __shfl_xor_sync(0xffffffffu, ps, 1);
            ps += __shfl_xor_sync(0xffffffffu, ps, 2);
            pq += __shfl_xor_sync(0xffffffffu, pq, 1);
            pq += __shfl_xor_sync(0xffffffffu, pq, 2);
            if ((lane & 3) == 0) {
                const int rl = mt * 16 + hh * 8 + rq;
                part_s[rl * 17 + wid] = ps;
                part_q[rl * 17 + wid] = pq;
            }
        }
    }
    __syncthreads();
    if (tid < 64) {
        float s = 0.f, q = 0.f;
#pragma unroll
        for (int w = 0; w < 16; w++) {
            s += part_s[tid * 17 + w];
            q += part_q[tid * 17 + w];
        }
        const float mean = s * (1.f / 512.f);
        const float var = q * (1.f / 512.f) - mean * mean;
        stat_m[tid] = mean;
        stat_i[tid] = rsqrtf(var + 1e-5f);
    }
    __syncthreads();
#pragma unroll
    for (int mt = 0; mt < 4; mt++) {
#pragma unroll
        for (int hh = 0; hh < 2; hh++) {
            const int rl = mt * 16 + hh * 8 + rq;
            const float mean = stat_m[rl];
            const float inv = stat_i[rl];
            const size_t rbase = (size_t)(m0 + rl) * 512;
#pragma unroll
            for (int nt = 0; nt < 4; nt++) {
                const int col = ec + nt * 8;
                float2 v;
                v.x = (acc[mt][nt][2 * hh + 0] - mean) * inv * g[col] + bl[col];
                v.y = (acc[mt][nt][2 * hh + 1] - mean) * inv * g[col + 1] + bl[col + 1];
                *(float2*)(out + rbase + col) = v;
            }
        }
    }
}

// ---------------- fp32 -> fp16 converts (single launch, 2x float4/thread) ----
#define X_N4  (MM * 512 / 4)
#define W1_N4 (1536 * 512 / 4)
#define W2_N4 (512 * 512 / 4)
#define W3_N4 (2048 * 512 / 4)
#define W4_N4 (512 * 2048 / 4)
#define CONV_TOT (X_N4 + W1_N4 + W2_N4 + W3_N4 + W4_N4)
__global__ void __launch_bounds__(256) conv_all_kernel(
    const float* __restrict__ x, const float* __restrict__ w1,
    const float* __restrict__ w2, const float* __restrict__ w3,
    const float* __restrict__ w4,
    __half* __restrict__ dx, __half* __restrict__ d1,
    __half* __restrict__ d2, __half* __restrict__ d3,
    __half* __restrict__ d4)
{
    int base = blockIdx.x * 512;
    const float* s; __half* d;
    if (base < X_N4) { s = x; d = dx; }
    else if ((base -= X_N4) < W1_N4) { s = w1; d = d1; }
    else if ((base -= W1_N4) < W2_N4) { s = w2; d = d2; }
    else if ((base -= W2_N4) < W3_N4) { s = w3; d = d3; }
    else { base -= W3_N4; s = w4; d = d4; }
    const int i0 = base + threadIdx.x;
    float4 v0 = ((const float4*)s)[i0];
    float4 v1 = ((const float4*)s)[i0 + 256];
    __half2* p0 = (__half2*)(d + (size_t)i0 * 4);
    p0[0] = __floats2half2_rn(v0.x, v0.y);
    p0[1] = __floats2half2_rn(v0.z, v0.w);
    __half2* p1 = (__half2*)(d + (size_t)(i0 + 256) * 4);
    p1[0] = __floats2half2_rn(v1.x, v1.y);
    p1[1] = __floats2half2_rn(v1.z, v1.w);
}

// ---------------- flash attention (fp16, 128-q tile, R10 version) ------------
#define AT_TILE (128 * 272)
#define ATTN_SMEM (5 * AT_TILE)

__global__ void __launch_bounds__(256) attn_kernel(
    const __half* __restrict__ qkv, __half* __restrict__ oh)
{
    const int qt = blockIdx.x, h = blockIdx.y, b = blockIdx.z;
    extern __shared__ char smc[];
    const uint32_t sQ = smem_u32(smc);
    const int tid = threadIdx.x;
    const int wid = tid >> 5, lane = tid & 31;
    const int q0 = wid * 16;
    const float sc = 0.08838834764831845f; // 1/sqrt(128)

    const __half* Qg = qkv + ((size_t)(b * 512 + qt * 128)) * 1536 + h * 128;
#pragma unroll
    for (int i = 0; i < 8; i++) {
        int slot = tid + i * 256;
        int r = slot >> 4, ch = slot & 15;
        cp16(sQ + r * 272 + ch * 16, Qg + (size_t)r * 1536 + ch * 8);
    }
    asm volatile("cp.async.commit_group;" ::: "memory");

    {
        const __half* Kg = qkv + ((size_t)(b * 512)) * 1536 + 512 + h * 128;
        const __half* Vg = Kg + 512;
#pragma unroll
        for (int i = 0; i < 8; i++) {
            int slot = tid + i * 256;
            int r = slot >> 4, ch = slot & 15;
            cp16(sQ + AT_TILE + r * 272 + ch * 16, Kg + (size_t)r * 1536 + ch * 8);
            cp16(sQ + 3 * AT_TILE + r * 272 + ch * 16, Vg + (size_t)r * 1536 + ch * 8);
        }
        asm volatile("cp.async.commit_group;" ::: "memory");
    }

    float m_[2] = {-1e30f, -1e30f};
    float l_[2] = {0.f, 0.f};
    float o[16][4];
#pragma unroll
    for (int nt = 0; nt < 16; nt++)
#pragma unroll
        for (int k = 0; k < 4; k++) o[nt][k] = 0.f;

    for (int kt = 0; kt < 4; kt++) {
        __syncthreads();
        if (kt + 1 < 4) {
            const __half* Kg = qkv + ((size_t)(b * 512 + (kt + 1) * 128)) * 1536
                               + 512 + h * 128;
            const __half* Vg = Kg + 512;
            const uint32_t bK = sQ + (1 + ((kt + 1) & 1)) * AT_TILE;
            const uint32_t bV = sQ + (3 + ((kt + 1) & 1)) * AT_TILE;
#pragma unroll
            for (int i = 0; i < 8; i++) {
                int slot = tid + i * 256;
                int r = slot >> 4, ch = slot & 15;
                cp16(bK + r * 272 + ch * 16, Kg + (size_t)r * 1536 + ch * 8);
                cp16(bV + r * 272 + ch * 16, Vg + (size_t)r * 1536 + ch * 8);
            }
            asm volatile("cp.async.commit_group;" ::: "memory");
            asm volatile("cp.async.wait_group 1;" ::: "memory");
        } else {
            asm volatile("cp.async.wait_group 0;" ::: "memory");
        }
        __syncthreads();

        const uint32_t sK = sQ + (1 + (kt & 1)) * AT_TILE;
        const uint32_t sV = sQ + (3 + (kt & 1)) * AT_TILE;

        float s[16][4];
#pragma unroll
        for (int nt = 0; nt < 16; nt++)
#pragma unroll
            for (int k = 0; k < 4; k++) s[nt][k] = 0.f;

#pragma unroll
        for (int j = 0; j < 8; j++) {
            uint32_t qa[4];
            LDSM4(qa, sQ + (q0 + (lane & 15)) * 272 + j * 32 + ((lane >> 4) & 1) * 16);
#pragma unroll
            for (int p = 0; p < 8; p++) {
                uint32_t kb[4];
                LDSM4(kb, sK + (p * 16 + (lane & 7) + ((lane >> 4) & 1) * 8) * 272
                            + j * 32 + ((lane >> 3) & 1) * 16);
                mma_f16(s[2 * p + 0], qa, kb[0], kb[1]);
                mma_f16(s[2 * p + 1], qa, kb[2], kb[3]);
            }
        }

        float mx0 = -1e30f, mx1 = -1e30f;
#pragma unroll
        for (int nt = 0; nt < 16; nt++) {
            mx0 = fmaxf(mx0, fmaxf(s[nt][0], s[nt][1]));
            mx1 = fmaxf(mx1, fmaxf(s[nt][2], s[nt][3]));
        }
        mx0 = fmaxf(mx0, __shfl_xor_sync(0xffffffffu, mx0, 1));
        mx0 = fmaxf(mx0, __shfl_xor_sync(0xffffffffu, mx0, 2));
        mx1 = fmaxf(mx1, __shfl_xor_sync(0xffffffffu, mx1, 1));
        mx1 = fmaxf(mx1, __shfl_xor_sync(0xffffffffu, mx1, 2));
        float mn0 = fmaxf(m_[0], mx0), mn1 = fmaxf(m_[1], mx1);
        float c0 = __expf(sc * (m_[0] - mn0)), c1 = __expf(sc * (m_[1] - mn1));
        m_[0] = mn0; m_[1] = mn1;
        l_[0] *= c0; l_[1] *= c1;
#pragma unroll
        for (int nt = 0; nt < 16; nt++) {
            o[nt][0] *= c0; o[nt][1] *= c0;
            o[nt][2] *= c1; o[nt][3] *= c1;
        }
        float ls0 = 0.f, ls1 = 0.f;
#pragma unroll
        for (int nt = 0; nt < 16; nt++) {
            s[nt][0] = __expf(sc * (s[nt][0] - mn0));
            s[nt][1] = __expf(sc * (s[nt][1] - mn0));
            s[nt][2] = __expf(sc * (s[nt][2] - mn1));
            s[nt][3] = __expf(sc * (s[nt][3] - mn1));
            ls0 += s[nt][0] + s[nt][1];
            ls1 += s[nt][2] + s[nt][3];
        }
        l_[0] += ls0; l_[1] += ls1;

#pragma unroll
        for (int j = 0; j < 8; j++) {
            uint32_t pa[4];
            pa[0] = packh2(s[2 * j][0], s[2 * j][1]);
            pa[1] = packh2(s[2 * j][2], s[2 * j][3]);
            pa[2] = packh2(s[2 * j + 1][0], s[2 * j + 1][1]);
            pa[3] = packh2(s[2 * j + 1][2], s[2 * j + 1][3]);
#pragma unroll
            for (int p = 0; p < 8; p++) {
                uint32_t vb[4];
                LDSM4T(vb, sV + (j * 16 + (lane & 7) + ((lane >> 3) & 1) * 8) * 272
                             + p * 32 + ((lane >> 4) & 1) * 16);
                mma_f16(o[2 * p + 0], pa, vb[0], vb[1]);
                mma_f16(o[2 * p + 1], pa, vb[2], vb[3]);
            }
        }
    }

    l_[0] += __shfl_xor_sync(0xffffffffu, l_[0], 1);
    l_[0] += __shfl_xor_sync(0xffffffffu, l_[0], 2);
    l_[1] += __shfl_xor_sync(0xffffffffu, l_[1], 1);
    l_[1] += __shfl_xor_sync(0xffffffffu, l_[1], 2);
    const float i0 = 1.0f / l_[0], i1 = 1.0f / l_[1];
    const size_t mrow = (size_t)(b * 512 + qt * 128 + q0 + (lane >> 2));
#pragma unroll
    for (int nt = 0; nt < 16; nt++) {
        const int col = h * 128 + nt * 8 + 2 * (lane & 3);
        *(__half2*)(oh + mrow * 512 + col) =
            __floats2half2_rn(o[nt][0] * i0, o[nt][1] * i0);
        *(__half2*)(oh + (mrow + 8) * 512 + col) =
            __floats2half2_rn(o[nt][2] * i1, o[nt][3] * i1);
    }
}

// ---------------- fully fused: LN1 + LN3 + qin + quantum + qout --------------
__global__ void __launch_bounds__(256) ln_quantum_kernel(
    const float* __restrict__ y,
    const float* __restrict__ g1, const float* __restrict__ b1,
    const float* __restrict__ g3, const float* __restrict__ b3,
    const float* __restrict__ qin_w, const float* __restrict__ qin_b,
    const float* __restrict__ qw,
    const float* __restrict__ qout_w, const float* __restrict__ qout_b,
    float* __restrict__ x2, __half* __restrict__ x2h)
{
    __shared__ float qin_s[8 * 512];
    __shared__ float qw_s[8][512];
    __shared__ float qb_s[512];
    const int tid = threadIdx.x;
    for (int t = tid; t < 4096; t += 256) {
        qin_s[t] = qin_w[t];
        int n = t >> 3, i = t & 7;
        qw_s[i][n] = qout_w[t];
    }
    for (int t = tid; t < 512; t += 256) qb_s[t] = qout_b[t];
    __syncthreads();

    const int row = blockIdx.x * 8 + (tid >> 5);
    const int lane = tid & 31;
    const float* yr = y + (size_t)row * 512;

    float xv[16];
#pragma unroll
    for (int j = 0; j < 16; j++) xv[j] = yr[lane + j * 32];

    float s = 0.f, sq = 0.f;
#pragma unroll
    for (int j = 0; j < 16; j++) { s += xv[j]; sq += xv[j] * xv[j]; }
    s = warp_sum(s); sq = warp_sum(sq);
    float mean = s * (1.f / 512.f);
    float var = sq * (1.f / 512.f) - mean * mean;
    float inv = rsqrtf(var + 1e-5f);
#pragma unroll
    for (int j = 0; j < 16; j++) {
        const int n = lane + j * 32;
        xv[j] = (xv[j] - mean) * inv * g1[n] + b1[n];
    }

    s = 0.f; sq = 0.f;
#pragma unroll
    for (int j = 0; j < 16; j++) { s += xv[j]; sq += xv[j] * xv[j]; }
    s = warp_sum(s); sq = warp_sum(sq);
    mean = s * (1.f / 512.f);
    var = sq * (1.f / 512.f) - mean * mean;
    inv = rsqrtf(var + 1e-5f);
    float xs[16];
#pragma unroll
    for (int j = 0; j < 16; j++) {
        const int n = lane + j * 32;
        xs[j] = (xv[j] - mean) * inv * g3[n] + b3[n];
    }

    float ang[8];
#pragma unroll
    for (int q = 0; q < 8; q++) {
        float d = 0.f;
#pragma unroll
        for (int j = 0; j < 16; j++) d += xs[j] * qin_s[q * 512 + lane + j * 32];
        d = warp_sum(d);
        ang[q] = d + qin_b[q];
    }

    float v0r[8], v0i[8], v1r[8], v1i[8];
#pragma unroll
    for (int w = 0; w < 8; w++) {
        float hh = 0.5f * ang[w];
        float c = cosf(hh), sn = sinf(hh);
        v0r[w] = c * c; v0i[w] = -sn * c;
        v1r[w] = sn * sn; v1i[w] = -sn * c;
    }
    float ar[8], ai[8];
#pragma unroll
    for (int k = 0; k < 8; k++) {
        int sidx = (lane << 3) | k;
        float pr = 1.f, pi = 0.f;
#pragma unroll
        for (int w = 0; w < 8; w++) {
            int bit = (sidx >> (7 - w)) & 1;
            float br = bit ? v1r[w] : v0r[w];
            float bi = bit ? v1i[w] : v0i[w];
            float nr = pr * br - pi * bi;
            pi = pr * bi + pi * br;
            pr = nr;
        }
        ar[k] = pr; ai[k] = pi;
    }
    for (int l = 0; l < 4; l++) {
        const float* wl = qw + l * 16;
#pragma unroll
        for (int i = 0; i < 8; i++) {
            const int bbit = 7 - i;
            {
                float hh = 0.5f * wl[i];
                float c = cosf(hh), sn = sinf(hh);
                if (bbit >= 3) {
                    const int msk = 1 << (bbit - 3);
#pragma unroll
                    for (int k = 0; k < 8; k++) {
                        float pr = __shfl_xor_sync(0xffffffffu, ar[k], msk);
                        float pi = __shfl_xor_sync(0xffffffffu, ai[k], msk);
                        float nr = c * ar[k] + sn * pi;
                        float ni = c * ai[k] - sn * pr;
                        ar[k] = nr; ai[k] = ni;
                    }
                } else {
                    const int str = 1 << bbit;
#pragma unroll
                    for (int k0 = 0; k0 < 8; k0++) {
                        if ((k0 & str) == 0) {
                            const int k1 = k0 | str;
                            float n0r = c * ar[k0] + sn * ai[k1];
                            float n0i = c * ai[k0] - sn * ar[k1];
                            float n1r = c * ar[k1] + sn * ai[k0];
                            float n1i = c * ai[k1] - sn * ar[k0];
                            ar[k0] = n0r; ai[k0] = n0i;
                            ar[k1] = n1r; ai[k1] = n1i;
                        }
                    }
                }
            }
            {
                float hh = 0.5f * wl[8 + i];
                float c = cosf(hh), sn = sinf(hh);
#pragma unroll
                for (int k = 0; k < 8; k++) {
                    int sidx = (lane << 3) | k;
                    float sg = ((sidx >> bbit) & 1) ? sn : -sn;
                    float nr = ar[k] * c - ai[k] * sg;
                    float ni = ai[k] * c + ar[k] * sg;
                    ar[k] = nr; ai[k] = ni;
                }
            }
        }
#pragma unroll
        for (int ctrl = 0; ctrl < 7; ctrl++) {
            const int bc = 7 - ctrl, bt = bc - 1;
            if (bt >= 3) {
                const int msk = 1 << (bt - 3);
                const int cbit = (lane >> (bc - 3)) & 1;
#pragma unroll
                for (int k = 0; k < 8; k++) {
                    float pr = __shfl_xor_sync(0xffffffffu, ar[k], msk);
                    float pi = __shfl_xor_sync(0xffffffffu, ai[k], msk);
                    if (cbit) { ar[k] = pr; ai[k] = pi; }
                }
            } else if (bt == 2) {
                if (lane & 1) {
#pragma unroll
                    for (int k = 0; k < 4; k++) {
                        float tr = ar[k], ti = ai[k];
                        ar[k] = ar[k + 4]; ai[k] = ai[k + 4];
                        ar[k + 4] = tr; ai[k + 4] = ti;
                    }
                }
            } else {
#pragma unroll
                for (int k = 0; k < 8; k++) {
                    if (((k >> bc) & 1) == 1 && ((k >> bt) & 1) == 0) {
                        const int k2 = k | (1 << bt);
                        float tr = ar[k], ti = ai[k];
                        ar[k] = ar[k2]; ai[k] = ai[k2];
                        ar[k2] = tr; ai[k2] = ti;
                    }
                }
            }
        }
    }
    float zp[8];
#pragma unroll
    for (int i = 0; i < 8; i++) zp[i] = 0.f;
#pragma unroll
    for (int k = 0; k < 8; k++) {
        int sidx = (lane << 3) | k;
        float p = ar[k] * ar[k] + ai[k] * ai[k];
#pragma unroll
        for (int i = 0; i < 8; i++)
            zp[i] += ((sidx >> (7 - i)) & 1) ? -p : p;
    }
#pragma unroll
    for (int off = 16; off >= 1; off >>= 1)
#pragma unroll
        for (int i = 0; i < 8; i++)
            zp[i] += __shfl_xor_sync(0xffffffffu, zp[i], off);

    const size_t base = (size_t)row * 512;
#pragma unroll
    for (int j = 0; j < 16; j++) {
        const int n = lane + j * 32;
        float v = xv[j] + qb_s[n];
#pragma unroll
        for (int i = 0; i < 8; i++) v += zp[i] * qw_s[i][n];
        x2[base + n] = v;
        x2h[base + n] = __float2half_rn(v);
    }
}

// ---------------- launch -----------------------------------------------------
extern "C" void kernel_launch(void* const* d_in, const int* in_sizes, int n_in,
                              void* d_out, int out_size)
{
    const float* x          = (const float*)d_in[0];
    const float* attn_in_w  = (const float*)d_in[1];
    const float* attn_in_b  = (const float*)d_in[2];
    const float* attn_out_w = (const float*)d_in[3];
    const float* attn_out_b = (const float*)d_in[4];
    const float* ln1_g      = (const float*)d_in[5];
    const float* ln1_b      = (const float*)d_in[6];
    const float* ln2_g      = (const float*)d_in[7];
    const float* ln2_b      = (const float*)d_in[8];
    const float* ln3_g      = (const float*)d_in[9];
    const float* ln3_b      = (const float*)d_in[10];
    const float* qin_w      = (const float*)d_in[11];
    const float* qin_b      = (const float*)d_in[12];
    const float* qweights   = (const float*)d_in[13];
    const float* qout_w     = (const float*)d_in[14];
    const float* qout_b     = (const float*)d_in[15];
    const float* ffn_w1     = (const float*)d_in[16];
    const float* ffn_b1     = (const float*)d_in[17];
    const float* ffn_w2     = (const float*)d_in[18];
    const float* ffn_b2     = (const float*)d_in[19];
    float* out = (float*)d_out;

    float *y, *x2;
    __half *qkvh, *xh, *ah, *x2h, *hh, *w1h, *w2h, *w3h, *w4h;
    cudaGetSymbolAddress((void**)&y,    g_y);
    cudaGetSymbolAddress((void**)&x2,   g_x2);
    cudaGetSymbolAddress((void**)&qkvh, g_qkvh);
    cudaGetSymbolAddress((void**)&xh,   g_xh);
    cudaGetSymbolAddress((void**)&ah,   g_ah);
    cudaGetSymbolAddress((void**)&x2h,  g_x2h);
    cudaGetSymbolAddress((void**)&hh,   g_hh);
    cudaGetSymbolAddress((void**)&w1h,  g_w1h);
    cudaGetSymbolAddress((void**)&w2h,  g_w2h);
    cudaGetSymbolAddress((void**)&w3h,  g_w3h);
    cudaGetSymbolAddress((void**)&w4h,  g_w4h);

    cudaFuncSetAttribute(attn_kernel,
                         cudaFuncAttributeMaxDynamicSharedMemorySize, ATTN_SMEM);
    cudaFuncSetAttribute(tc_gemm<1>,
                         cudaFuncAttributeMaxDynamicSharedMemorySize, GEMM_SMEM);
    cudaFuncSetAttribute(tc_gemm<2>,
                         cudaFuncAttributeMaxDynamicSharedMemorySize, GEMM_SMEM);
    cudaFuncSetAttribute(tc_gemm<3>,
                         cudaFuncAttributeMaxDynamicSharedMemorySize, GEMM_SMEM);
    cudaFuncSetAttribute(tc_gemm_ln,
                         cudaFuncAttributeMaxDynamicSharedMemorySize, GEMM_LN_SMEM);

    // 0. converts (single launch)
    conv_all_kernel<<<CONV_TOT / 512, 256>>>(
        x, attn_in_w, attn_out_w, ffn_w1, ffn_w2, xh, w1h, w2h, w3h, w4h);

    // 1. QKV projection -> fp16
    tc_gemm<3><<<dim3(6, 128), 512, GEMM_SMEM>>>(
        xh, w1h, attn_in_b, nullptr, nullptr, qkvh, MM, 1536, 512);
    // 2. flash attention -> fp16
    attn_kernel<<<dim3(4, 4, 32), 256, ATTN_SMEM>>>(qkvh, ah);
    // 3. output projection + residual -> fp32
    tc_gemm<1><<<dim3(2, 128), 512, GEMM_SMEM>>>(
        ah, w2h, attn_out_b, x, y, nullptr, MM, 512, 512);
    // 4. LN1 + LN3 + qin + quantum + qout (fully fused)
    ln_quantum_kernel<<<MM / 8, 256>>>(y, ln1_g, ln1_b, ln3_g, ln3_b,
                                       qin_w, qin_b, qweights,
                                       qout_w, qout_b, x2, x2h);
    // 5. FFN up + gelu -> fp16
    tc_gemm<2><<<dim3(8, 128), 512, GEMM_SMEM>>>(
        x2h, w3h, ffn_b1, nullptr, nullptr, hh, MM, 2048, 512);
    // 6. FFN down + residual + LN2 fused -> final output
    tc_gemm_ln<<<MM / 64, 512, GEMM_LN_SMEM>>>(
        hh, w4h, ffn_b2, x2, ln2_g, ln2_b, out, 2048);
}

// round 16
// speedup vs baseline: 1.0216x; 1.0216x over previous
#include <cuda_runtime.h>
#include <cuda_bf16.h>
#include <cuda_fp16.h>
#include <cstdint>
#include <math.h>

#define MM 16384   // B*S = 32*512

// ---------------- scratch (device globals; no allocation allowed) -------------
__device__ float g_y[MM * 512];
__device__ float g_y2[MM * 512];

__device__ __half g_qkvh[MM * 1536];
__device__ __half g_xh[MM * 512];
__device__ __half g_ah[MM * 512];      // attention out
__device__ __half g_x2h[MM * 512];
__device__ __half g_hh[MM * 2048];     // ffn hidden
__device__ __half g_w1h[1536 * 512];
__device__ __half g_w2h[512 * 512];
__device__ __half g_w3h[2048 * 512];
__device__ __half g_w4h[512 * 2048];

// ---------------- helpers ----------------------------------------------------
__device__ __forceinline__ uint32_t smem_u32(const void* p) {
    uint32_t a;
    asm("{ .reg .u64 t; cvta.to.shared.u64 t, %1; cvt.u32.u64 %0, t; }"
        : "=r"(a) : "l"(p));
    return a;
}
#define SWZ128(o) ((o) ^ (((o) >> 3) & 0x70))

__device__ __forceinline__ void cp16(uint32_t dst, const void* src) {
    asm volatile("cp.async.cg.shared.global [%0], [%1], 16;"
                 :: "r"(dst), "l"(src) : "memory");
}
#define LDSM4(r, addr) \
    asm volatile("ldmatrix.sync.aligned.m8n8.x4.shared.b16 {%0,%1,%2,%3}, [%4];" \
                 : "=r"((r)[0]), "=r"((r)[1]), "=r"((r)[2]), "=r"((r)[3]) : "r"(addr))
#define LDSM4T(r, addr) \
    asm volatile("ldmatrix.sync.aligned.m8n8.x4.trans.shared.b16 {%0,%1,%2,%3}, [%4];" \
                 : "=r"((r)[0]), "=r"((r)[1]), "=r"((r)[2]), "=r"((r)[3]) : "r"(addr))

__device__ __forceinline__ void mma_f16(float* c, const uint32_t* a,
                                        uint32_t b0, uint32_t b1) {
    asm volatile(
        "mma.sync.aligned.m16n8k16.row.col.f32.f16.f16.f32 "
        "{%0,%1,%2,%3}, {%4,%5,%6,%7}, {%8,%9}, {%0,%1,%2,%3};"
        : "+f"(c[0]), "+f"(c[1]), "+f"(c[2]), "+f"(c[3])
        : "r"(a[0]), "r"(a[1]), "r"(a[2]), "r"(a[3]), "r"(b0), "r"(b1));
}
__device__ __forceinline__ uint32_t packh2(float a, float b) {
    __half2 h = __floats2half2_rn(a, b);
    return *reinterpret_cast<uint32_t*>(&h);
}
__device__ __forceinline__ float warp_sum(float v) {
    v += __shfl_xor_sync(0xffffffffu, v, 16);
    v += __shfl_xor_sync(0xffffffffu, v, 8);
    v += __shfl_xor_sync(0xffffffffu, v, 4);
    v += __shfl_xor_sync(0xffffffffu, v, 2);
    v += __shfl_xor_sync(0xffffffffu, v, 1);
    return v;
}

// ---------------- HMMA GEMM (fp16, 128x256 CTA, 512 thr, K-chunk 128) --------
// best measured config (R10): 2-stage, 1 barrier per 128-K chunk.
// MODE: 1 = bias + fp32 residual -> fp32; 2 = bias + gelu -> fp16;
//       3 = bias -> fp16;          4 = bias + fp16 residual -> fp32
#define STG_BYTES 98304   // [Ah0 16K][Ah1 16K][Bh0 32K][Bh1 32K]
#define GEMM_SMEM (2 * STG_BYTES)

__device__ __forceinline__ void ld_chunk128(
    uint32_t sbase,
    const __half* __restrict__ A, const __half* __restrict__ B,
    int m0, int n0, int K, int k0, int tid)
{
#pragma unroll
    for (int half = 0; half < 2; half++) {
        const int kh = k0 + half * 64;
        const uint32_t aB = sbase + half * 16384;
        const uint32_t bB = sbase + 32768 + half * 32768;
#pragma unroll
        for (int t = 0; t < 2; t++) {
            int slot = tid + t * 512;
            int r = slot >> 3, c = slot & 7;
            cp16(aB + SWZ128(r * 128 + c * 16), A + (size_t)(m0 + r) * K + kh + c * 8);
        }
#pragma unroll
        for (int t = 0; t < 4; t++) {
            int slot = tid + t * 512;
            int r = slot >> 3, c = slot & 7;
            cp16(bB + SWZ128(r * 128 + c * 16), B + (size_t)(n0 + r) * K + kh + c * 8);
        }
    }
    asm volatile("cp.async.commit_group;" ::: "memory");
}

template <int MODE>
__global__ void __launch_bounds__(512) tc_gemm(
    const __half* __restrict__ A, const __half* __restrict__ B,
    const float* __restrict__ bias, const void* __restrict__ res,
    float* __restrict__ Cf, __half* __restrict__ Ch,
    int M, int N, int K)
{
    extern __shared__ char sm[];
    const uint32_t sb = smem_u32(sm);
    const int tid = threadIdx.x;
    const int wid = tid >> 5, lane = tid & 31;
    const int wm = wid & 1, wn = wid >> 1;   // 2 x 8 warp grid
    const int m0 = blockIdx.y * 128, n0 = blockIdx.x * 256;

    float acc[4][4][4];
#pragma unroll
    for (int i = 0; i < 4; i++)
#pragma unroll
        for (int j = 0; j < 4; j++)
#pragma unroll
            for (int k = 0; k < 4; k++) acc[i][j][k] = 0.f;

    const int nch = K >> 7;
    ld_chunk128(sb, A, B, m0, n0, K, 0, tid);

    const int a_row = wm * 64 + (lane & 15);
    const int a_colb = ((lane >> 4) & 1) * 16;
    const int b_row = wn * 32 + (lane & 7) + ((lane >> 4) & 1) * 8;
    const int b_colb = ((lane >> 3) & 1) * 16;

    for (int c = 0; c < nch; c++) {
        asm volatile("cp.async.wait_group 0;" ::: "memory");
        __syncthreads();
        if (c + 1 < nch)
            ld_chunk128(sb + ((c + 1) & 1) * STG_BYTES,
                        A, B, m0, n0, K, (c + 1) << 7, tid);

        const uint32_t stg = sb + (c & 1) * STG_BYTES;

#pragma unroll
        for (int ks = 0; ks < 8; ks++) {
            const int half = ks >> 2, ksl = ks & 3;
            const uint32_t sA = stg + half * 16384;
            const uint32_t sB = stg + 32768 + half * 32768;
            uint32_t af[4][4];
#pragma unroll
            for (int mt = 0; mt < 4; mt++)
                LDSM4(af[mt], sA + SWZ128((a_row + mt * 16) * 128 + ksl * 32 + a_colb));
            uint32_t bf[2][4];
#pragma unroll
            for (int np = 0; np < 2; np++)
                LDSM4(bf[np], sB + SWZ128((b_row + np * 16) * 128 + ksl * 32 + b_colb));
#pragma unroll
            for (int mt = 0; mt < 4; mt++)
#pragma unroll
                for (int nt = 0; nt < 4; nt++) {
                    const int np = nt >> 1, hf = (nt & 1) * 2;
                    mma_f16(acc[mt][nt], af[mt], bf[np][hf], bf[np][hf + 1]);
                }
        }
    }

    // epilogue
    const int er0 = m0 + wm * 64 + (lane >> 2);
    const int ec0 = n0 + wn * 32 + 2 * (lane & 3);
#pragma unroll
    for (int mt = 0; mt < 4; mt++) {
#pragma unroll
        for (int nt = 0; nt < 4; nt++) {
            const int col = ec0 + nt * 8;
            const float b0 = bias[col], b1 = bias[col + 1];
#pragma unroll
            for (int hh = 0; hh < 2; hh++) {
                const int row = er0 + mt * 16 + hh * 8;
                float v0 = acc[mt][nt][2 * hh + 0] + b0;
                float v1 = acc[mt][nt][2 * hh + 1] + b1;
                size_t off = (size_t)row * N + col;
                if (MODE == 1 || MODE == 4) {
                    if (MODE == 1) {
                        const float* rf = (const float*)res;
                        v0 += rf[off];
                        v1 += rf[off + 1];
                    } else {
                        __half2 rr = *(const __half2*)((const __half*)res + off);
                        v0 += __half2float(rr.x);
                        v1 += __half2float(rr.y);
                    }
                    float2 v; v.x = v0; v.y = v1;
                    *(float2*)(Cf + off) = v;
                } else {
                    if (MODE == 2) {
                        v0 = 0.5f * v0 * (1.0f + erff(v0 * 0.70710678118654752f));
                        v1 = 0.5f * v1 * (1.0f + erff(v1 * 0.70710678118654752f));
                    }
                    *(__half2*)(Ch + off) = __floats2half2_rn(v0, v1);
                }
            }
        }
    }
}

// ---------------- fp32 -> fp16 converts (single launch, 2x float4/thread) ----
#define X_N4  (MM * 512 / 4)
#define W1_N4 (1536 * 512 / 4)
#define W2_N4 (512 * 512 / 4)
#define W3_N4 (2048 * 512 / 4)
#define W4_N4 (512 * 2048 / 4)
#define CONV_TOT (X_N4 + W1_N4 + W2_N4 + W3_N4 + W4_N4)
__global__ void __launch_bounds__(256) conv_all_kernel(
    const float* __restrict__ x, const float* __restrict__ w1,
    const float* __restrict__ w2, const float* __restrict__ w3,
    const float* __restrict__ w4,
    __half* __restrict__ dx, __half* __restrict__ d1,
    __half* __restrict__ d2, __half* __restrict__ d3,
    __half* __restrict__ d4)
{
    int base = blockIdx.x * 512;
    const float* s; __half* d;
    if (base < X_N4) { s = x; d = dx; }
    else if ((base -= X_N4) < W1_N4) { s = w1; d = d1; }
    else if ((base -= W1_N4) < W2_N4) { s = w2; d = d2; }
    else if ((base -= W2_N4) < W3_N4) { s = w3; d = d3; }
    else { base -= W3_N4; s = w4; d = d4; }
    const int i0 = base + threadIdx.x;
    float4 v0 = ((const float4*)s)[i0];
    float4 v1 = ((const float4*)s)[i0 + 256];
    __half2* p0 = (__half2*)(d + (size_t)i0 * 4);
    p0[0] = __floats2half2_rn(v0.x, v0.y);
    p0[1] = __floats2half2_rn(v0.z, v0.w);
    __half2* p1 = (__half2*)(d + (size_t)(i0 + 256) * 4);
    p1[0] = __floats2half2_rn(v1.x, v1.y);
    p1[1] = __floats2half2_rn(v1.z, v1.w);
}

// ---------------- flash attention (fp16, 128-q tile, R10 version) ------------
#define AT_TILE (128 * 272)
#define ATTN_SMEM (5 * AT_TILE)

__global__ void __launch_bounds__(256) attn_kernel(
    const __half* __restrict__ qkv, __half* __restrict__ oh)
{
    const int qt = blockIdx.x, h = blockIdx.y, b = blockIdx.z;
    extern __shared__ char smc[];
    const uint32_t sQ = smem_u32(smc);
    const int tid = threadIdx.x;
    const int wid = tid >> 5, lane = tid & 31;
    const int q0 = wid * 16;
    const float sc = 0.08838834764831845f; // 1/sqrt(128)

    const __half* Qg = qkv + ((size_t)(b * 512 + qt * 128)) * 1536 + h * 128;
#pragma unroll
    for (int i = 0; i < 8; i++) {
        int slot = tid + i * 256;
        int r = slot >> 4, ch = slot & 15;
        cp16(sQ + r * 272 + ch * 16, Qg + (size_t)r * 1536 + ch * 8);
    }
    asm volatile("cp.async.commit_group;" ::: "memory");

    {
        const __half* Kg = qkv + ((size_t)(b * 512)) * 1536 + 512 + h * 128;
        const __half* Vg = Kg + 512;
#pragma unroll
        for (int i = 0; i < 8; i++) {
            int slot = tid + i * 256;
            int r = slot >> 4, ch = slot & 15;
            cp16(sQ + AT_TILE + r * 272 + ch * 16, Kg + (size_t)r * 1536 + ch * 8);
            cp16(sQ + 3 * AT_TILE + r * 272 + ch * 16, Vg + (size_t)r * 1536 + ch * 8);
        }
        asm volatile("cp.async.commit_group;" ::: "memory");
    }

    float m_[2] = {-1e30f, -1e30f};
    float l_[2] = {0.f, 0.f};
    float o[16][4];
#pragma unroll
    for (int nt = 0; nt < 16; nt++)
#pragma unroll
        for (int k = 0; k < 4; k++) o[nt][k] = 0.f;

    for (int kt = 0; kt < 4; kt++) {
        __syncthreads();
        if (kt + 1 < 4) {
            const __half* Kg = qkv + ((size_t)(b * 512 + (kt + 1) * 128)) * 1536
                               + 512 + h * 128;
            const __half* Vg = Kg + 512;
            const uint32_t bK = sQ + (1 + ((kt + 1) & 1)) * AT_TILE;
            const uint32_t bV = sQ + (3 + ((kt + 1) & 1)) * AT_TILE;
#pragma unroll
            for (int i = 0; i < 8; i++) {
                int slot = tid + i * 256;
                int r = slot >> 4, ch = slot & 15;
                cp16(bK + r * 272 + ch * 16, Kg + (size_t)r * 1536 + ch * 8);
                cp16(bV + r * 272 + ch * 16, Vg + (size_t)r * 1536 + ch * 8);
            }
            asm volatile("cp.async.commit_group;" ::: "memory");
            asm volatile("cp.async.wait_group 1;" ::: "memory");
        } else {
            asm volatile("cp.async.wait_group 0;" ::: "memory");
        }
        __syncthreads();

        const uint32_t sK = sQ + (1 + (kt & 1)) * AT_TILE;
        const uint32_t sV = sQ + (3 + (kt & 1)) * AT_TILE;

        float s[16][4];
#pragma unroll
        for (int nt = 0; nt < 16; nt++)
#pragma unroll
            for (int k = 0; k < 4; k++) s[nt][k] = 0.f;

#pragma unroll
        for (int j = 0; j < 8; j++) {
            uint32_t qa[4];
            LDSM4(qa, sQ + (q0 + (lane & 15)) * 272 + j * 32 + ((lane >> 4) & 1) * 16);
#pragma unroll
            for (int p = 0; p < 8; p++) {
                uint32_t kb[4];
                LDSM4(kb, sK + (p * 16 + (lane & 7) + ((lane >> 4) & 1) * 8) * 272
                            + j * 32 + ((lane >> 3) & 1) * 16);
                mma_f16(s[2 * p + 0], qa, kb[0], kb[1]);
                mma_f16(s[2 * p + 1], qa, kb[2], kb[3]);
            }
        }

        float mx0 = -1e30f, mx1 = -1e30f;
#pragma unroll
        for (int nt = 0; nt < 16; nt++) {
            mx0 = fmaxf(mx0, fmaxf(s[nt][0], s[nt][1]));
            mx1 = fmaxf(mx1, fmaxf(s[nt][2], s[nt][3]));
        }
        mx0 = fmaxf(mx0, __shfl_xor_sync(0xffffffffu, mx0, 1));
        mx0 = fmaxf(mx0, __shfl_xor_sync(0xffffffffu, mx0, 2));
        mx1 = fmaxf(mx1, __shfl_xor_sync(0xffffffffu, mx1, 1));
        mx1 = fmaxf(mx1, __shfl_xor_sync(0xffffffffu, mx1, 2));
        float mn0 = fmaxf(m_[0], mx0), mn1 = fmaxf(m_[1], mx1);
        float c0 = __expf(sc * (m_[0] - mn0)), c1 = __expf(sc * (m_[1] - mn1));
        m_[0] = mn0; m_[1] = mn1;
        l_[0] *= c0; l_[1] *= c1;
#pragma unroll
        for (int nt = 0; nt < 16; nt++) {
            o[nt][0] *= c0; o[nt][1] *= c0;
            o[nt][2] *= c1; o[nt][3] *= c1;
        }
        float ls0 = 0.f, ls1 = 0.f;
#pragma unroll
        for (int nt = 0; nt < 16; nt++) {
            s[nt][0] = __expf(sc * (s[nt][0] - mn0));
            s[nt][1] = __expf(sc * (s[nt][1] - mn0));
            s[nt][2] = __expf(sc * (s[nt][2] - mn1));
            s[nt][3] = __expf(sc * (s[nt][3] - mn1));
            ls0 += s[nt][0] + s[nt][1];
            ls1 += s[nt][2] + s[nt][3];
        }
        l_[0] += ls0; l_[1] += ls1;

#pragma unroll
        for (int j = 0; j < 8; j++) {
            uint32_t pa[4];
            pa[0] = packh2(s[2 * j][0], s[2 * j][1]);
            pa[1] = packh2(s[2 * j][2], s[2 * j][3]);
            pa[2] = packh2(s[2 * j + 1][0], s[2 * j + 1][1]);
            pa[3] = packh2(s[2 * j + 1][2], s[2 * j + 1][3]);
#pragma unroll
            for (int p = 0; p < 8; p++) {
                uint32_t vb[4];
                LDSM4T(vb, sV + (j * 16 + (lane & 7) + ((lane >> 3) & 1) * 8) * 272
                             + p * 32 + ((lane >> 4) & 1) * 16);
                mma_f16(o[2 * p + 0], pa, vb[0], vb[1]);
                mma_f16(o[2 * p + 1], pa, vb[2], vb[3]);
            }
        }
    }

    l_[0] += __shfl_xor_sync(0xffffffffu, l_[0], 1);
    l_[0] += __shfl_xor_sync(0xffffffffu, l_[0], 2);
    l_[1] += __shfl_xor_sync(0xffffffffu, l_[1], 1);
    l_[1] += __shfl_xor_sync(0xffffffffu, l_[1], 2);
    const float i0 = 1.0f / l_[0], i1 = 1.0f / l_[1];
    const size_t mrow = (size_t)(b * 512 + qt * 128 + q0 + (lane >> 2));
#pragma unroll
    for (int nt = 0; nt < 16; nt++) {
        const int col = h * 128 + nt * 8 + 2 * (lane & 3);
        *(__half2*)(oh + mrow * 512 + col) =
            __floats2half2_rn(o[nt][0] * i0, o[nt][1] * i0);
        *(__half2*)(oh + (mrow + 8) * 512 + col) =
            __floats2half2_rn(o[nt][2] * i1, o[nt][3] * i1);
    }
}

// ---------------- LN2 (warp-per-row, float4) ----------------------------------
__global__ void __launch_bounds__(256) ln_kernel(
    const float* __restrict__ in, const float* __restrict__ g,
    const float* __restrict__ b, float* __restrict__ out)
{
    const int row = blockIdx.x * 8 + (threadIdx.x >> 5);
    const int lane = threadIdx.x & 31;
    const float4* xr = (const float4*)(in + (size_t)row * 512);
    float4 v[4];
#pragma unroll
    for (int j = 0; j < 4; j++) v[j] = xr[lane + j * 32];
    float s = 0.f, sq = 0.f;
#pragma unroll
    for (int j = 0; j < 4; j++) {
        s  += v[j].x + v[j].y + v[j].z + v[j].w;
        sq += v[j].x * v[j].x + v[j].y * v[j].y
            + v[j].z * v[j].z + v[j].w * v[j].w;
    }
    s = warp_sum(s); sq = warp_sum(sq);
    const float mean = s * (1.f / 512.f);
    const float var = sq * (1.f / 512.f) - mean * mean;
    const float inv = rsqrtf(var + 1e-5f);
    float4* orow = (float4*)(out + (size_t)row * 512);
    const float4* g4 = (const float4*)g;
    const float4* b4 = (const float4*)b;
#pragma unroll
    for (int j = 0; j < 4; j++) {
        const float4 gg = g4[lane + j * 32];
        const float4 bb = b4[lane + j * 32];
        float4 r;
        r.x = (v[j].x - mean) * inv * gg.x + bb.x;
        r.y = (v[j].y - mean) * inv * gg.y + bb.y;
        r.z = (v[j].z - mean) * inv * gg.z + bb.z;
        r.w = (v[j].w - mean) * inv * gg.w + bb.w;
        orow[lane + j * 32] = r;
    }
}

// ---------------- fully fused: LN1 + LN3 + qin + quantum + qout --------------
// writes x2 ONLY as fp16 (the fp32 copy is eliminated; FFN-down residual
// reads the fp16 plane).
__global__ void __launch_bounds__(256) ln_quantum_kernel(
    const float* __restrict__ y,
    const float* __restrict__ g1, const float* __restrict__ b1,
    const float* __restrict__ g3, const float* __restrict__ b3,
    const float* __restrict__ qin_w, const float* __restrict__ qin_b,
    const float* __restrict__ qw,
    const float* __restrict__ qout_w, const float* __restrict__ qout_b,
    __half* __restrict__ x2h)
{
    __shared__ float qin_s[8 * 512];
    __shared__ float qw_s[8][512];
    __shared__ float qb_s[512];
    const int tid = threadIdx.x;
    for (int t = tid; t < 4096; t += 256) {
        qin_s[t] = qin_w[t];
        int n = t >> 3, i = t & 7;
        qw_s[i][n] = qout_w[t];
    }
    for (int t = tid; t < 512; t += 256) qb_s[t] = qout_b[t];
    __syncthreads();

    const int row = blockIdx.x * 8 + (tid >> 5);
    const int lane = tid & 31;
    const float* yr = y + (size_t)row * 512;

    float xv[16];
#pragma unroll
    for (int j = 0; j < 16; j++) xv[j] = yr[lane + j * 32];

    float s = 0.f, sq = 0.f;
#pragma unroll
    for (int j = 0; j < 16; j++) { s += xv[j]; sq += xv[j] * xv[j]; }
    s = warp_sum(s); sq = warp_sum(sq);
    float mean = s * (1.f / 512.f);
    float var = sq * (1.f / 512.f) - mean * mean;
    float inv = rsqrtf(var + 1e-5f);
#pragma unroll
    for (int j = 0; j < 16; j++) {
        const int n = lane + j * 32;
        xv[j] = (xv[j] - mean) * inv * g1[n] + b1[n];
    }

    s = 0.f; sq = 0.f;
#pragma unroll
    for (int j = 0; j < 16; j++) { s += xv[j]; sq += xv[j] * xv[j]; }
    s = warp_sum(s); sq = warp_sum(sq);
    mean = s * (1.f / 512.f);
    var = sq * (1.f / 512.f) - mean * mean;
    inv = rsqrtf(var + 1e-5f);
    float xs[16];
#pragma unroll
    for (int j = 0; j < 16; j++) {
        const int n = lane + j * 32;
        xs[j] = (xv[j] - mean) * inv * g3[n] + b3[n];
    }

    float ang[8];
#pragma unroll
    for (int q = 0; q < 8; q++) {
        float d = 0.f;
#pragma unroll
        for (int j = 0; j < 16; j++) d += xs[j] * qin_s[q * 512 + lane + j * 32];
        d = warp_sum(d);
        ang[q] = d + qin_b[q];
    }

    float v0r[8], v0i[8], v1r[8], v1i[8];
#pragma unroll
    for (int w = 0; w < 8; w++) {
        float hh = 0.5f * ang[w];
        float c = cosf(hh), sn = sinf(hh);
        v0r[w] = c * c; v0i[w] = -sn * c;
        v1r[w] = sn * sn; v1i[w] = -sn * c;
    }
    float ar[8], ai[8];
#pragma unroll
    for (int k = 0; k < 8; k++) {
        int sidx = (lane << 3) | k;
        float pr = 1.f, pi = 0.f;
#pragma unroll
        for (int w = 0; w < 8; w++) {
            int bit = (sidx >> (7 - w)) & 1;
            float br = bit ? v1r[w] : v0r[w];
            float bi = bit ? v1i[w] : v0i[w];
            float nr = pr * br - pi * bi;
            pi = pr * bi + pi * br;
            pr = nr;
        }
        ar[k] = pr; ai[k] = pi;
    }
    for (int l = 0; l < 4; l++) {
        const float* wl = qw + l * 16;
#pragma unroll
        for (int i = 0; i < 8; i++) {
            const int bbit = 7 - i;
            {
                float hh = 0.5f * wl[i];
                float c = cosf(hh), sn = sinf(hh);
                if (bbit >= 3) {
                    const int msk = 1 << (bbit - 3);
#pragma unroll
                    for (int k = 0; k < 8; k++) {
                        float pr = __shfl_xor_sync(0xffffffffu, ar[k], msk);
                        float pi = __shfl_xor_sync(0xffffffffu, ai[k], msk);
                        float nr = c * ar[k] + sn * pi;
                        float ni = c * ai[k] - sn * pr;
                        ar[k] = nr; ai[k] = ni;
                    }
                } else {
                    const int str = 1 << bbit;
#pragma unroll
                    for (int k0 = 0; k0 < 8; k0++) {
                        if ((k0 & str) == 0) {
                            const int k1 = k0 | str;
                            float n0r = c * ar[k0] + sn * ai[k1];
                            float n0i = c * ai[k0] - sn * ar[k1];
                            float n1r = c * ar[k1] + sn * ai[k0];
                            float n1i = c * ai[k1] - sn * ar[k0];
                            ar[k0] = n0r; ai[k0] = n0i;
                            ar[k1] = n1r; ai[k1] = n1i;
                        }
                    }
                }
            }
            {
                float hh = 0.5f * wl[8 + i];
                float c = cosf(hh), sn = sinf(hh);
#pragma unroll
                for (int k = 0; k < 8; k++) {
                    int sidx = (lane << 3) | k;
                    float sg = ((sidx >> bbit) & 1) ? sn : -sn;
                    float nr = ar[k] * c - ai[k] * sg;
                    float ni = ai[k] * c + ar[k] * sg;
                    ar[k] = nr; ai[k] = ni;
                }
            }
        }
#pragma unroll
        for (int ctrl = 0; ctrl < 7; ctrl++) {
            const int bc = 7 - ctrl, bt = bc - 1;
            if (bt >= 3) {
                const int msk = 1 << (bt - 3);
                const int cbit = (lane >> (bc - 3)) & 1;
#pragma unroll
                for (int k = 0; k < 8; k++) {
                    float pr = __shfl_xor_sync(0xffffffffu, ar[k], msk);
                    float pi = __shfl_xor_sync(0xffffffffu, ai[k], msk);
                    if (cbit) { ar[k] = pr; ai[k] = pi; }
                }
            } else if (bt == 2) {
                if (lane & 1) {
#pragma unroll
                    for (int k = 0; k < 4; k++) {
                        float tr = ar[k], ti = ai[k];
                        ar[k] = ar[k + 4]; ai[k] = ai[k + 4];
                        ar[k + 4] = tr; ai[k + 4] = ti;
                    }
                }
            } else {
#pragma unroll
                for (int k = 0; k < 8; k++) {
                    if (((k >> bc) & 1) == 1 && ((k >> bt) & 1) == 0) {
                        const int k2 = k | (1 << bt);
                        float tr = ar[k], ti = ai[k];
                        ar[k] = ar[k2]; ai[k] = ai[k2];
                        ar[k2] = tr; ai[k2] = ti;
                    }
                }
            }
        }
    }
    float zp[8];
#pragma unroll
    for (int i = 0; i < 8; i++) zp[i] = 0.f;
#pragma unroll
    for (int k = 0; k < 8; k++) {
        int sidx = (lane << 3) | k;
        float p = ar[k] * ar[k] + ai[k] * ai[k];
#pragma unroll
        for (int i = 0; i < 8; i++)
            zp[i] += ((sidx >> (7 - i)) & 1) ? -p : p;
    }
#pragma unroll
    for (int off = 16; off >= 1; off >>= 1)
#pragma unroll
        for (int i = 0; i < 8; i++)
            zp[i] += __shfl_xor_sync(0xffffffffu, zp[i], off);

    const size_t base = (size_t)row * 512;
#pragma unroll
    for (int j = 0; j < 16; j++) {
        const int n = lane + j * 32;
        float v = xv[j] + qb_s[n];
#pragma unroll
        for (int i = 0; i < 8; i++) v += zp[i] * qw_s[i][n];
        x2h[base + n] = __float2half_rn(v);
    }
}

// ---------------- launch -----------------------------------------------------
extern "C" void kernel_launch(void* const* d_in, const int* in_sizes, int n_in,
                              void* d_out, int out_size)
{
    const float* x          = (const float*)d_in[0];
    const float* attn_in_w  = (const float*)d_in[1];
    const float* attn_in_b  = (const float*)d_in[2];
    const float* attn_out_w = (const float*)d_in[3];
    const float* attn_out_b = (const float*)d_in[4];
    const float* ln1_g      = (const float*)d_in[5];
    const float* ln1_b      = (const float*)d_in[6];
    const float* ln2_g      = (const float*)d_in[7];
    const float* ln2_b      = (const float*)d_in[8];
    const float* ln3_g      = (const float*)d_in[9];
    const float* ln3_b      = (const float*)d_in[10];
    const float* qin_w      = (const float*)d_in[11];
    const float* qin_b      = (const float*)d_in[12];
    const float* qweights   = (const float*)d_in[13];
    const float* qout_w     = (const float*)d_in[14];
    const float* qout_b     = (const float*)d_in[15];
    const float* ffn_w1     = (const float*)d_in[16];
    const float* ffn_b1     = (const float*)d_in[17];
    const float* ffn_w2     = (const float*)d_in[18];
    const float* ffn_b2     = (const float*)d_in[19];
    float* out = (float*)d_out;

    float *y, *y2;
    __half *qkvh, *xh, *ah, *x2h, *hh, *w1h, *w2h, *w3h, *w4h;
    cudaGetSymbolAddress((void**)&y,    g_y);
    cudaGetSymbolAddress((void**)&y2,   g_y2);
    cudaGetSymbolAddress((void**)&qkvh, g_qkvh);
    cudaGetSymbolAddress((void**)&xh,   g_xh);
    cudaGetSymbolAddress((void**)&ah,   g_ah);
    cudaGetSymbolAddress((void**)&x2h,  g_x2h);
    cudaGetSymbolAddress((void**)&hh,   g_hh);
    cudaGetSymbolAddress((void**)&w1h,  g_w1h);
    cudaGetSymbolAddress((void**)&w2h,  g_w2h);
    cudaGetSymbolAddress((void**)&w3h,  g_w3h);
    cudaGetSymbolAddress((void**)&w4h,  g_w4h);

    cudaFuncSetAttribute(attn_kernel,
                         cudaFuncAttributeMaxDynamicSharedMemorySize, ATTN_SMEM);
    cudaFuncSetAttribute(tc_gemm<1>,
                         cudaFuncAttributeMaxDynamicSharedMemorySize, GEMM_SMEM);
    cudaFuncSetAttribute(tc_gemm<2>,
                         cudaFuncAttributeMaxDynamicSharedMemorySize, GEMM_SMEM);
    cudaFuncSetAttribute(tc_gemm<3>,
                         cudaFuncAttributeMaxDynamicSharedMemorySize, GEMM_SMEM);
    cudaFuncSetAttribute(tc_gemm<4>,
                         cudaFuncAttributeMaxDynamicSharedMemorySize, GEMM_SMEM);

    // 0. converts (single launch)
    conv_all_kernel<<<CONV_TOT / 512, 256>>>(
        x, attn_in_w, attn_out_w, ffn_w1, ffn_w2, xh, w1h, w2h, w3h, w4h);

    // 1. QKV projection -> fp16
    tc_gemm<3><<<dim3(6, 128), 512, GEMM_SMEM>>>(
        xh, w1h, attn_in_b, nullptr, nullptr, qkvh, MM, 1536, 512);
    // 2. flash attention -> fp16
    attn_kernel<<<dim3(4, 4, 32), 256, ATTN_SMEM>>>(qkvh, ah);
    // 3. output projection + residual (fp32 x) -> fp32
    tc_gemm<1><<<dim3(2, 128), 512, GEMM_SMEM>>>(
        ah, w2h, attn_out_b, x, y, nullptr, MM, 512, 512);
    // 4. LN1 + LN3 + qin + quantum + qout (fully fused) -> x2 fp16 only
    ln_quantum_kernel<<<MM / 8, 256>>>(y, ln1_g, ln1_b, ln3_g, ln3_b,
                                       qin_w, qin_b, qweights,
                                       qout_w, qout_b, x2h);
    // 5. FFN up + gelu -> fp16
    tc_gemm<2><<<dim3(8, 128), 512, GEMM_SMEM>>>(
        x2h, w3h, ffn_b1, nullptr, nullptr, hh, MM, 2048, 512);
    // 6. FFN down + residual (fp16 x2h) -> fp32
    tc_gemm<4><<<dim3(2, 128), 512, GEMM_SMEM>>>(
        hh, w4h, ffn_b2, x2h, y2, nullptr, MM, 512, 2048);
    // 7. LN2 -> output (warp-per-row)
    ln_kernel<<<MM / 8, 256>>>(y2, ln2_g, ln2_b, out);
}